// round 16
// baseline (speedup 1.0000x reference)
#include <cuda_runtime.h>
#include <cstdint>

// Problem constants (match reference_code)
#define USER_NUM  1000000
#define EMBED_DIM 64
#define BATCH     16384

// FM scoring: out[e] = w[u] + w[i] + b + dot(V[u], V[i])
//   (0.5*sum((Vu+Vi)^2 - Vu^2 - Vi^2) == sum(Vu*Vi))
// INPUT is int32 on the wire (JAX x64-off downgrades int64->int32).
//
// FINAL FORM — measured best, reproduced 3x on identical source:
//   wall {6.624, 6.656, 6.88} us, kernel {5.95, 5.95, 6.14} us, 1454 GB/s.
//
// Evidence base (R2-R15):
//  - Pinned at the chip's random-line service wall (~1.45TB/s), invariant
//    across LDG / cp.async / TMA-bulk / TMA-gather4, occupancy 20-86%,
//    per-thread MLP 2-9, load widths 64-256b, prefetch/evict hints, and
//    dual-engine splits. DRAM traffic equals the logical minimum (8.65MB).
//  - Linear terms (w[u], w[i], b) on lane 0, issued after the gathers:
//    independent chain overlapped with the shuffle reduce (folding them
//    into other lanes puts them on the reduce critical path: -8%, R13).
//  - 32-bit offsets (max 70.4M elements < 2^31) remove IMAD.WIDE chains.
//  - Wall - kernel gap (~0.65us) is fixed graph-replay overhead.
__global__ void __launch_bounds__(256) fm_score_kernel(
    const int*   __restrict__ inp,   // [BATCH, 2] int32
    const float* __restrict__ w,     // [USER_NUM + ITEM_NUM]
    const float* __restrict__ bptr,  // [1]
    const float* __restrict__ V,     // [USER_NUM + ITEM_NUM, 64]
    float*       __restrict__ out)   // [BATCH]
{
    const int gid  = blockIdx.x * blockDim.x + threadIdx.x;
    const int elem = gid >> 4;       // 16 lanes per element (grid is exact)
    const int lane = gid & 15;

    // Both indices in one 64-bit broadcast load.
    const int2 idx = __ldg(reinterpret_cast<const int2*>(inp) + elem);
    const unsigned u = (unsigned)idx.x;                 // < 100000
    const unsigned i = (unsigned)idx.y + USER_NUM;      // < 1100000

    const float* up = V + u * (unsigned)EMBED_DIM;
    const float* ip = V + i * (unsigned)EMBED_DIM;

    // Two 128-bit gathers back-to-back (rows are 256B-aligned).
    const float4 a = __ldg(reinterpret_cast<const float4*>(up) + lane);
    const float4 c = __ldg(reinterpret_cast<const float4*>(ip) + lane);

    // Linear terms on lane 0: independent chain, overlapped with the
    // gathers and the reduction, consumed only at the final store.
    float wsum = 0.0f;
    if (lane == 0)
        wsum = __ldg(&w[u]) + __ldg(&w[i]) + __ldg(&bptr[0]);

    float dot = a.x * c.x + a.y * c.y + a.z * c.z + a.w * c.w;

    // Reduce across the 16-lane group (contiguous within the warp).
    #pragma unroll
    for (int off = 8; off > 0; off >>= 1)
        dot += __shfl_xor_sync(0xffffffffu, dot, off);

    if (lane == 0)
        out[elem] = wsum + dot;
}

extern "C" void kernel_launch(void* const* d_in, const int* in_sizes, int n_in,
                              void* d_out, int out_size)
{
    const int*   inp = (const int*)d_in[0];    // INPUT int32 [BATCH,2]
    const float* w   = (const float*)d_in[1];  // w
    const float* b   = (const float*)d_in[2];  // b
    const float* V   = (const float*)d_in[3];  // V
    float*       out = (float*)d_out;          // [BATCH,1] float32

    const int threads = 256;
    const int blocks  = (BATCH * 16) / threads;   // 1024, exact
    fm_score_kernel<<<blocks, threads>>>(inp, w, b, V, out);
}

// round 17
// speedup vs baseline: 1.0385x; 1.0385x over previous
#include <cuda_runtime.h>
#include <cstdint>

// Problem constants (match reference_code)
#define USER_NUM  1000000
#define EMBED_DIM 64
#define BATCH     16384

// FM scoring: out[e] = w[u] + w[i] + b + dot(V[u], V[i])
//   (0.5*sum((Vu+Vi)^2 - Vu^2 - Vi^2) == sum(Vu*Vi))
// INPUT is int32 on the wire (JAX x64-off downgrades int64->int32).
//
// FINAL FORM — identical source measured 4x:
//   wall {6.624, 6.656, 6.88, 6.912} us (replay-overhead jitter, uncorrelated
//   with kernel time), kernel {5.95, 5.95, 6.14, 5.92} us @ ~1.45 TB/s.
//
// Evidence base (R2-R16):
//  - Pinned at the chip's random-line service wall (~1.45TB/s), invariant
//    across LDG / cp.async / TMA-bulk / TMA-gather4, occupancy 20-86%,
//    per-thread MLP 2-9, load widths 64-256b, prefetch/evict hints, and
//    dual-engine splits. DRAM traffic equals the logical minimum (8.65MB):
//    98K random line requests at ~34cyc aggregate service = ~5.9us floor.
//  - Linear terms (w[u], w[i], b) on lane 0, issued after the gathers:
//    independent chain overlapped with the shuffle reduce (folding them
//    into other lanes puts them on the reduce critical path: -8%, R13).
//  - 32-bit offsets (max 70.4M elements < 2^31) remove IMAD.WIDE chains.
__global__ void __launch_bounds__(256) fm_score_kernel(
    const int*   __restrict__ inp,   // [BATCH, 2] int32
    const float* __restrict__ w,     // [USER_NUM + ITEM_NUM]
    const float* __restrict__ bptr,  // [1]
    const float* __restrict__ V,     // [USER_NUM + ITEM_NUM, 64]
    float*       __restrict__ out)   // [BATCH]
{
    const int gid  = blockIdx.x * blockDim.x + threadIdx.x;
    const int elem = gid >> 4;       // 16 lanes per element (grid is exact)
    const int lane = gid & 15;

    // Both indices in one 64-bit broadcast load.
    const int2 idx = __ldg(reinterpret_cast<const int2*>(inp) + elem);
    const unsigned u = (unsigned)idx.x;                 // < 100000
    const unsigned i = (unsigned)idx.y + USER_NUM;      // < 1100000

    const float* up = V + u * (unsigned)EMBED_DIM;
    const float* ip = V + i * (unsigned)EMBED_DIM;

    // Two 128-bit gathers back-to-back (rows are 256B-aligned).
    const float4 a = __ldg(reinterpret_cast<const float4*>(up) + lane);
    const float4 c = __ldg(reinterpret_cast<const float4*>(ip) + lane);

    // Linear terms on lane 0: independent chain, overlapped with the
    // gathers and the reduction, consumed only at the final store.
    float wsum = 0.0f;
    if (lane == 0)
        wsum = __ldg(&w[u]) + __ldg(&w[i]) + __ldg(&bptr[0]);

    float dot = a.x * c.x + a.y * c.y + a.z * c.z + a.w * c.w;

    // Reduce across the 16-lane group (contiguous within the warp).
    #pragma unroll
    for (int off = 8; off > 0; off >>= 1)
        dot += __shfl_xor_sync(0xffffffffu, dot, off);

    if (lane == 0)
        out[elem] = wsum + dot;
}

extern "C" void kernel_launch(void* const* d_in, const int* in_sizes, int n_in,
                              void* d_out, int out_size)
{
    const int*   inp = (const int*)d_in[0];    // INPUT int32 [BATCH,2]
    const float* w   = (const float*)d_in[1];  // w
    const float* b   = (const float*)d_in[2];  // b
    const float* V   = (const float*)d_in[3];  // V
    float*       out = (float*)d_out;          // [BATCH,1] float32

    const int threads = 256;
    const int blocks  = (BATCH * 16) / threads;   // 1024, exact
    fm_score_kernel<<<blocks, threads>>>(inp, w, b, V, out);
}